// round 16
// baseline (speedup 1.0000x reference)
#include <cuda_runtime.h>
#include <math.h>

constexpr int BB      = 16;
constexpr int T       = 512;
constexpr int D       = 512;
constexpr int DH      = 64;
constexpr int BH      = 128;          // BB*HEADS
constexpr int DEPTH   = 8;
constexpr int NHASH   = 4;
constexpr int NB      = 8;
constexpr int NCHUNK  = 32;
constexpr int FF      = 2048;
constexpr int NLABELS = 2;
constexpr int ROWS    = BB * T;       // 8192
constexpr int NT      = NHASH * T;    // 2048
constexpr float MASK_VAL = -50000.0f;

// ---------------------------------------------------------------------------
// Device scratch. NOTE: these must NEVER be passed directly as host-side
// kernel arguments (host shadow address + ATS silently reads host memory).
// Either reference them inside device code, or pass addresses obtained via
// cudaGetSymbolAddress.
// ---------------------------------------------------------------------------
__device__ float g_x1 [ROWS * D];
__device__ float g_x2 [ROWS * D];
__device__ float g_xn [ROWS * D];
__device__ float g_qk [ROWS * D];
__device__ float g_v  [ROWS * D];
__device__ float g_ctx[ROWS * D];
__device__ float g_ff [ROWS * FF];
__device__ float g_so  [(size_t)BH * NT * DH];
__device__ float g_P   [(size_t)BH * NT * 128];
__device__ float g_slog[BH * NT];
__device__ float g_rn  [BH * NT];
__device__ int   g_st  [BH * NT];
__device__ int   g_undo[BH * NT];
__device__ int   g_bucket[BH * NT];

__device__ __forceinline__ float gelu_exact(float x) {
    return 0.5f * x * (1.0f + erff(x * 0.70710678118654752f));
}

// ---------------------------------------------------------------------------
// Embedding (writes g_x1/g_x2 internally — proven-working pattern)
// ---------------------------------------------------------------------------
__global__ void embed_kernel(const int* __restrict__ ids,
                             const float* __restrict__ tok,
                             const float* __restrict__ pos)
{
    size_t i = (size_t)blockIdx.x * blockDim.x + threadIdx.x;
    int bt = (int)(i >> 9);
    int d  = (int)(i & 511);
    int t  = bt & (T - 1);
    float v = tok[(size_t)ids[bt] * D + d] + pos[(size_t)t * D + d];
    g_x1[i] = v;
    g_x2[i] = v;
}

// ---------------------------------------------------------------------------
// LayerNorm: X,Y are real device addresses (via cudaGetSymbolAddress);
// g,b are pre-offset input pointers.
// ---------------------------------------------------------------------------
__global__ void ln_kernel(const float* __restrict__ X,
                          const float* __restrict__ gg,
                          const float* __restrict__ bb,
                          float* __restrict__ Y)
{
    __shared__ float red[256];
    const int row = blockIdx.x, tid = threadIdx.x;
    const float* x = X + (size_t)row * D;
    float v0 = x[tid], v1 = x[tid + 256];
    red[tid] = v0 + v1;
    __syncthreads();
    for (int o = 128; o > 0; o >>= 1) { if (tid < o) red[tid] += red[tid + o]; __syncthreads(); }
    float mean = red[0] * (1.0f / D);
    __syncthreads();
    float d0 = v0 - mean, d1 = v1 - mean;
    red[tid] = d0 * d0 + d1 * d1;
    __syncthreads();
    for (int o = 128; o > 0; o >>= 1) { if (tid < o) red[tid] += red[tid + o]; __syncthreads(); }
    float rstd = rsqrtf(red[0] * (1.0f / D) + 1e-5f);
    float* y = Y + (size_t)row * D;
    y[tid]       = d0 * rstd * gg[tid]       + bb[tid];
    y[tid + 256] = d1 * rstd * gg[tid + 256] + bb[tid + 256];
}

// ---------------------------------------------------------------------------
// Matmul, 4 rows per block: C[M,N] = A@B (+bias)(+gelu)(+residual).
// EPI: 0 none, 2 bias+gelu, 3 bias+residual (Res may alias C elementwise).
// ---------------------------------------------------------------------------
template<int EPI>
__global__ void nmm_kernel(const float* __restrict__ A,
                           const float* __restrict__ Bm,
                           float* __restrict__ C,
                           const float* __restrict__ bias,
                           const float* __restrict__ Res,
                           int N, int K)
{
    int m0 = blockIdx.y * 4;
    int n  = blockIdx.x * 128 + threadIdx.x;
    const float* a0 = A + (size_t)m0 * K;
    const float* a1 = a0 + K;
    const float* a2 = a1 + K;
    const float* a3 = a2 + K;
    float c0 = 0.f, c1 = 0.f, c2 = 0.f, c3 = 0.f;
#pragma unroll 4
    for (int k = 0; k < K; k++) {
        float bv = Bm[(size_t)k * N + n];
        c0 += a0[k] * bv;
        c1 += a1[k] * bv;
        c2 += a2[k] * bv;
        c3 += a3[k] * bv;
    }
    float bs = (EPI >= 2) ? bias[n] : 0.0f;
    float r[4] = {c0, c1, c2, c3};
#pragma unroll
    for (int i = 0; i < 4; i++) {
        size_t o = (size_t)(m0 + i) * N + n;
        float v = r[i];
        if (EPI >= 2) v += bs;
        if (EPI == 2) v = gelu_exact(v);
        if (EPI == 3) v += Res[o];
        C[o] = v;
    }
}

// ---------------------------------------------------------------------------
// LSH buckets: one thread per (bh, h, t); rot pre-offset per layer.
// ---------------------------------------------------------------------------
__global__ void bucket_kernel(const float* __restrict__ rot)
{
    int gid = blockIdx.x * blockDim.x + threadIdx.x;   // < BH*NHASH*T
    int t  = gid & 511;
    int h  = (gid >> 9) & 3;
    int bh = gid >> 11;
    const float* qkb = g_qk + (size_t)(bh >> 3) * T * D + (bh & 7) * DH;

    float s0 = 0.f, s1 = 0.f, s2 = 0.f, s3 = 0.f;
#pragma unroll 8
    for (int d = 0; d < DH; d++) {
        float q = qkb[(size_t)t * D + d];
        const float* rp = rot + d * (NHASH * 4) + h * 4;
        s0 += q * rp[0];
        s1 += q * rp[1];
        s2 += q * rp[2];
        s3 += q * rp[3];
    }
    float cand[8] = {s0, s1, s2, s3, -s0, -s1, -s2, -s3};
    float best = cand[0];
    int bi = 0;
#pragma unroll
    for (int j = 1; j < 8; j++)
        if (cand[j] > best) { best = cand[j]; bi = j; }
    g_bucket[gid] = bi + h * NB;
}

// ---------------------------------------------------------------------------
// Stable counting sort: key = bucket*T + t (unique); bucket id fixes the
// hash round (h = bucket/NB), so per-bucket ascending-t == argsort order.
// ---------------------------------------------------------------------------
__global__ void place_kernel()
{
    const int bh = blockIdx.x;
    __shared__ int counts[NCHUNK + 1];
    if (threadIdx.x <= NCHUNK) counts[threadIdx.x] = 0;
    __syncthreads();
    for (int i = threadIdx.x; i < NT; i += blockDim.x)
        atomicAdd(&counts[g_bucket[bh * NT + i] + 1], 1);
    __syncthreads();
    if (threadIdx.x == 0)
        for (int i = 1; i <= NCHUNK; i++) counts[i] += counts[i - 1];
    __syncthreads();
    if (threadIdx.x < NCHUNK) {
        int w = threadIdx.x;
        int h = w >> 3;
        int pos = counts[w];
        for (int t = 0; t < T; t++) {
            if (g_bucket[bh * NT + h * T + t] == w) {
                g_st  [bh * NT + pos]       = t;
                g_undo[bh * NT + h * T + t] = pos;
                pos++;
            }
        }
    }
}

__global__ void rnorm_kernel()
{
    int spg = blockIdx.x * blockDim.x + threadIdx.x;   // < BH*NT
    int bh = spg >> 11;
    int t = g_st[spg];
    const float* row = g_qk + (size_t)(bh >> 3) * T * D + (bh & 7) * DH
                       + (size_t)t * D;
    float s = 0.0f;
#pragma unroll 8
    for (int d = 0; d < DH; d++) { float x = row[d]; s += x * x; }
    g_rn[spg] = 1.0f / fmaxf(sqrtf(s), 1e-6f);
}

__global__ void dots_kernel()
{
    int gid = blockIdx.x * blockDim.x + threadIdx.x;   // < BH*NT*128
    int kj  = gid & 127;
    int spg = gid >> 7;
    int bh  = spg >> 11;
    int sp  = spg & (NT - 1);
    int c   = sp >> 6;
    int cprev = (c + NCHUNK - 1) & (NCHUNK - 1);
    int kpos = (kj < 64) ? (c * 64 + kj) : (cprev * 64 + (kj - 64));

    int tq  = g_st[bh * NT + sp];
    int tkk = g_st[bh * NT + kpos];
    const float* base = g_qk + (size_t)(bh >> 3) * T * D + (bh & 7) * DH;
    const float* qrow = base + (size_t)tq  * D;
    const float* krow = base + (size_t)tkk * D;

    float s = 0.0f;
#pragma unroll 8
    for (int d = 0; d < DH; d++) s += qrow[d] * krow[d];
    s = s * g_rn[bh * NT + kpos] * 0.125f;
    if (tkk == tq) s = MASK_VAL;
    g_P[(size_t)spg * 128 + kj] = s;
}

__global__ void softmax_kernel()
{
    int gid  = blockIdx.x * blockDim.x + threadIdx.x;
    int row  = gid >> 5;
    int lane = gid & 31;
    float* p = g_P + (size_t)row * 128;
    float v0 = p[lane], v1 = p[lane + 32], v2 = p[lane + 64], v3 = p[lane + 96];
    float m = fmaxf(fmaxf(v0, v1), fmaxf(v2, v3));
#pragma unroll
    for (int o = 16; o > 0; o >>= 1) m = fmaxf(m, __shfl_xor_sync(0xffffffffu, m, o));
    float e0 = expf(v0 - m), e1 = expf(v1 - m), e2 = expf(v2 - m), e3 = expf(v3 - m);
    float ss = e0 + e1 + e2 + e3;
#pragma unroll
    for (int o = 16; o > 0; o >>= 1) ss += __shfl_xor_sync(0xffffffffu, ss, o);
    float inv = 1.0f / ss;
    p[lane]      = e0 * inv;
    p[lane + 32] = e1 * inv;
    p[lane + 64] = e2 * inv;
    p[lane + 96] = e3 * inv;
    if (lane == 0) g_slog[row] = m + logf(ss);
}

__global__ void pv_kernel()
{
    int gid = blockIdx.x * blockDim.x + threadIdx.x;   // < BH*NT*64
    int e   = gid & 63;
    int spg = gid >> 6;
    int bh  = spg >> 11;
    int sp  = spg & (NT - 1);
    int c   = sp >> 6;
    int cprev = (c + NCHUNK - 1) & (NCHUNK - 1);

    const float* prow = g_P + (size_t)spg * 128;
    const int* stp = g_st + bh * NT;
    const float* vb = g_v + (size_t)(bh >> 3) * T * D + (bh & 7) * DH;

    float acc = 0.0f;
#pragma unroll 8
    for (int j = 0; j < 128; j++) {
        int kpos = (j < 64) ? (c * 64 + j) : (cprev * 64 + (j - 64));
        int tv = stp[kpos];
        acc += prow[j] * vb[(size_t)tv * D + e];
    }
    g_so[(size_t)spg * DH + e] = acc;
}

__global__ void merge_kernel()
{
    int gid = blockIdx.x * blockDim.x + threadIdx.x;
    int gwarp = gid >> 5, lane = gid & 31;
    int bh = gwarp >> 9;
    int t  = gwarp & (T - 1);
    int base = bh * NT;

    float lg[4]; int jj[4];
#pragma unroll
    for (int h = 0; h < 4; h++) {
        jj[h] = g_undo[base + h * T + t];
        lg[h] = g_slog[base + jj[h]];
    }
    float m = fmaxf(fmaxf(lg[0], lg[1]), fmaxf(lg[2], lg[3]));
    float e0 = expf(lg[0] - m), e1 = expf(lg[1] - m), e2 = expf(lg[2] - m), e3 = expf(lg[3] - m);
    float inv = 1.0f / (e0 + e1 + e2 + e3);
    float w0 = e0 * inv, w1 = e1 * inv, w2 = e2 * inv, w3 = e3 * inv;

    const float* s0 = g_so + (size_t)(base + jj[0]) * DH;
    const float* s1 = g_so + (size_t)(base + jj[1]) * DH;
    const float* s2 = g_so + (size_t)(base + jj[2]) * DH;
    const float* s3 = g_so + (size_t)(base + jj[3]) * DH;

    int b = bh >> 3, h8 = bh & 7;
    float* dst = g_ctx + (size_t)(b * T + t) * D + h8 * DH;
#pragma unroll
    for (int e = lane; e < DH; e += 32)
        dst[e] = w0 * s0[e] + w1 * s1[e] + w2 * s2[e] + w3 * s3[e];
}

__global__ void cls_kernel(const float* __restrict__ cw,
                           const float* __restrict__ cb,
                           float* __restrict__ out)
{
    int warp = threadIdx.x >> 5, lane = threadIdx.x & 31;
    int b = warp >> 1, n = warp & 1;
    const float* p1 = g_x1 + (size_t)b * T * D;
    const float* p2 = g_x2 + (size_t)b * T * D;
    float s = 0.0f;
    for (int d = lane; d < D; d += 32)
        s += (p1[d] + p2[d]) * cw[d * NLABELS + n];
#pragma unroll
    for (int o = 16; o > 0; o >>= 1) s += __shfl_xor_sync(0xffffffffu, s, o);
    if (lane == 0) out[b * NLABELS + n] = s + cb[n];
}

__global__ void outfill_kernel(float* out, int out_size)
{
    int i = 32 + blockIdx.x * blockDim.x + threadIdx.x;
    if (i < out_size) out[i] = 0.0f;
}

// ---------------------------------------------------------------------------
// Launch sequence. Dict input order, f32/i32 (all confirmed by R15 diag).
// Scratch addresses via cudaGetSymbolAddress (real device VAs).
// ---------------------------------------------------------------------------
extern "C" void kernel_launch(void* const* d_in, const int* in_sizes, int n_in,
                              void* d_out, int out_size)
{
    const int*   ids   = (const int*)  d_in[0];
    const float* tok   = (const float*)d_in[1];
    const float* pos   = (const float*)d_in[2];
    const float* rot   = (const float*)d_in[3];
    const float* Wqk   = (const float*)d_in[4];
    const float* Wv    = (const float*)d_in[5];
    const float* Wout  = (const float*)d_in[6];
    const float* bout  = (const float*)d_in[7];
    const float* lnf_s = (const float*)d_in[8];
    const float* lnf_b = (const float*)d_in[9];
    const float* lng_s = (const float*)d_in[10];
    const float* lng_b = (const float*)d_in[11];
    const float* fw1   = (const float*)d_in[12];
    const float* fb1   = (const float*)d_in[13];
    const float* fw2   = (const float*)d_in[14];
    const float* fb2   = (const float*)d_in[15];
    const float* cw    = (const float*)d_in[16];
    const float* cb    = (const float*)d_in[17];
    float* out = (float*)d_out;

    // Real device addresses of scratch buffers
    void *vp;
    float *p_x1, *p_x2, *p_xn, *p_qk, *p_v, *p_ctx, *p_ff;
    cudaGetSymbolAddress(&vp, g_x1);  p_x1  = (float*)vp;
    cudaGetSymbolAddress(&vp, g_x2);  p_x2  = (float*)vp;
    cudaGetSymbolAddress(&vp, g_xn);  p_xn  = (float*)vp;
    cudaGetSymbolAddress(&vp, g_qk);  p_qk  = (float*)vp;
    cudaGetSymbolAddress(&vp, g_v);   p_v   = (float*)vp;
    cudaGetSymbolAddress(&vp, g_ctx); p_ctx = (float*)vp;
    cudaGetSymbolAddress(&vp, g_ff);  p_ff  = (float*)vp;

    embed_kernel<<<(ROWS * D) / 256, 256>>>(ids, tok, pos);

    dim3 gD (D  / 128, ROWS / 4);
    dim3 gF1(FF / 128, ROWS / 4);
    dim3 gF2(D  / 128, ROWS / 4);

    for (int l = 0; l < DEPTH; l++) {
        const float* wqk = Wqk + (size_t)l * D * D;
        const float* wv  = Wv  + (size_t)l * D * D;
        const float* wo  = Wout + (size_t)l * D * D;
        const float* w1  = fw1 + (size_t)l * D * FF;
        const float* w2  = fw2 + (size_t)l * FF * D;

        ln_kernel<<<ROWS, 256>>>(p_x2, lnf_s + l * D, lnf_b + l * D, p_xn);
        nmm_kernel<0><<<gD, 128>>>(p_xn, wqk, p_qk, nullptr, nullptr, D, D);
        nmm_kernel<0><<<gD, 128>>>(p_xn, wv,  p_v,  nullptr, nullptr, D, D);
        bucket_kernel<<<(BH * NHASH * T) / 256, 256>>>(rot + (size_t)l * DH * NHASH * 4);
        place_kernel<<<BH, 256>>>();
        rnorm_kernel<<<(BH * NT) / 256, 256>>>();
        dots_kernel<<<(BH * NT * 128) / 256, 256>>>();
        softmax_kernel<<<(BH * NT * 32) / 256, 256>>>();
        pv_kernel<<<(BH * NT * 64) / 256, 256>>>();
        merge_kernel<<<(BH * T) / 8, 256>>>();
        nmm_kernel<3><<<gD, 128>>>(p_ctx, wo, p_x1, bout + l * D, p_x1, D, D);
        ln_kernel<<<ROWS, 256>>>(p_x1, lng_s + l * D, lng_b + l * D, p_xn);
        nmm_kernel<2><<<gF1, 128>>>(p_xn, w1, p_ff, fb1 + l * FF, nullptr, FF, D);
        nmm_kernel<3><<<gF2, 128>>>(p_ff, w2, p_x2, fb2 + l * D, p_x2, D, FF);
    }

    if (out_size > 32 && out_size <= (1 << 20)) {
        int extra = out_size - 32;
        outfill_kernel<<<(extra + 255) / 256, 256>>>(out, out_size);
    }
    cls_kernel<<<1, 1024>>>(cw, cb, out);
}

// round 17
// speedup vs baseline: 5.3147x; 5.3147x over previous
#include <cuda_runtime.h>
#include <math.h>

constexpr int BB      = 16;
constexpr int T       = 512;
constexpr int D       = 512;
constexpr int DH      = 64;
constexpr int BH      = 128;          // BB*HEADS
constexpr int DEPTH   = 8;
constexpr int NHASH   = 4;
constexpr int NB      = 8;
constexpr int NCHUNK  = 32;
constexpr int FF      = 2048;
constexpr int NLABELS = 2;
constexpr int ROWS    = BB * T;       // 8192
constexpr int NT      = NHASH * T;    // 2048
constexpr float MASK_VAL = -50000.0f;

// ---------------------------------------------------------------------------
// Device scratch. NEVER pass these directly as host-side kernel arguments
// (host shadow address + ATS reads host memory silently). Reference them in
// device code, or pass addresses from cudaGetSymbolAddress.
// ---------------------------------------------------------------------------
__device__ float g_x1 [ROWS * D];
__device__ float g_x2 [ROWS * D];
__device__ float g_xn [ROWS * D];
__device__ float g_qk [ROWS * D];
__device__ float g_v  [ROWS * D];
__device__ float g_ctx[ROWS * D];
__device__ float g_ff [ROWS * FF];
__device__ float g_so  [(size_t)BH * NT * DH];
__device__ float g_P   [(size_t)BH * NT * 128];
__device__ float g_slog[BH * NT];
__device__ float g_rn  [BH * NT];
__device__ int   g_st  [BH * NT];
__device__ int   g_undo[BH * NT];
__device__ int   g_bucket[BH * NT];

__device__ __forceinline__ float gelu_exact(float x) {
    return 0.5f * x * (1.0f + erff(x * 0.70710678118654752f));
}

// ---------------------------------------------------------------------------
// Embedding
// ---------------------------------------------------------------------------
__global__ void embed_kernel(const int* __restrict__ ids,
                             const float* __restrict__ tok,
                             const float* __restrict__ pos)
{
    size_t i = (size_t)blockIdx.x * blockDim.x + threadIdx.x;
    int bt = (int)(i >> 9);
    int d  = (int)(i & 511);
    int t  = bt & (T - 1);
    float v = tok[(size_t)ids[bt] * D + d] + pos[(size_t)t * D + d];
    g_x1[i] = v;
    g_x2[i] = v;
}

// ---------------------------------------------------------------------------
// LayerNorm (one block per row)
// ---------------------------------------------------------------------------
__global__ void ln_kernel(const float* __restrict__ X,
                          const float* __restrict__ gg,
                          const float* __restrict__ bb,
                          float* __restrict__ Y)
{
    __shared__ float red[256];
    const int row = blockIdx.x, tid = threadIdx.x;
    const float* x = X + (size_t)row * D;
    float v0 = x[tid], v1 = x[tid + 256];
    red[tid] = v0 + v1;
    __syncthreads();
    for (int o = 128; o > 0; o >>= 1) { if (tid < o) red[tid] += red[tid + o]; __syncthreads(); }
    float mean = red[0] * (1.0f / D);
    __syncthreads();
    float d0 = v0 - mean, d1 = v1 - mean;
    red[tid] = d0 * d0 + d1 * d1;
    __syncthreads();
    for (int o = 128; o > 0; o >>= 1) { if (tid < o) red[tid] += red[tid + o]; __syncthreads(); }
    float rstd = rsqrtf(red[0] * (1.0f / D) + 1e-5f);
    float* y = Y + (size_t)row * D;
    y[tid]       = d0 * rstd * gg[tid]       + bb[tid];
    y[tid + 256] = d1 * rstd * gg[tid + 256] + bb[tid + 256];
}

// ---------------------------------------------------------------------------
// Tiled SGEMM: C[M,N] = A[M,K] @ B[K,N] (+bias)(+gelu)(+residual).
// 128x128x8 tile, 8x8 per thread, 256 threads.
// EPI: 0 none, 2 bias+gelu, 3 bias+residual (Res may alias C elementwise).
// ---------------------------------------------------------------------------
template<int EPI>
__global__ __launch_bounds__(256, 2)
void sgemm_kernel(const float* __restrict__ A, const float* __restrict__ Bm,
                  float* __restrict__ C, const float* __restrict__ bias,
                  const float* __restrict__ Res, int N, int K)
{
    __shared__ float As[8][128];
    __shared__ float Bs[8][128];
    const int tid = threadIdx.x;
    const int tx = tid & 15, ty = tid >> 4;
    const int m0 = blockIdx.y * 128, n0 = blockIdx.x * 128;

    const int arow = tid >> 1;
    const int aseg = (tid & 1) * 4;
    const int brow = tid >> 5;
    const int bcol = (tid & 31) * 4;

    float acc[8][8];
#pragma unroll
    for (int i = 0; i < 8; i++)
#pragma unroll
        for (int j = 0; j < 8; j++) acc[i][j] = 0.0f;

    for (int k0 = 0; k0 < K; k0 += 8) {
        float4 av = *reinterpret_cast<const float4*>(A  + (size_t)(m0 + arow) * K + k0 + aseg);
        float4 bv = *reinterpret_cast<const float4*>(Bm + (size_t)(k0 + brow) * N + n0 + bcol);
        As[aseg + 0][arow] = av.x;
        As[aseg + 1][arow] = av.y;
        As[aseg + 2][arow] = av.z;
        As[aseg + 3][arow] = av.w;
        *reinterpret_cast<float4*>(&Bs[brow][bcol]) = bv;
        __syncthreads();
#pragma unroll
        for (int k = 0; k < 8; k++) {
            float a[8], b[8];
#pragma unroll
            for (int i = 0; i < 8; i++) a[i] = As[k][ty + 16 * i];
#pragma unroll
            for (int j = 0; j < 8; j++) b[j] = Bs[k][tx + 16 * j];
#pragma unroll
            for (int i = 0; i < 8; i++)
#pragma unroll
                for (int j = 0; j < 8; j++) acc[i][j] += a[i] * b[j];
        }
        __syncthreads();
    }

#pragma unroll
    for (int i = 0; i < 8; i++) {
        int row = m0 + ty + 16 * i;
#pragma unroll
        for (int j = 0; j < 8; j++) {
            int col = n0 + tx + 16 * j;
            float v = acc[i][j];
            if (EPI >= 2) v += bias[col];
            if (EPI == 2) v = gelu_exact(v);
            if (EPI == 3) v += Res[(size_t)row * N + col];
            C[(size_t)row * N + col] = v;
        }
    }
}

// ---------------------------------------------------------------------------
// LSH buckets (unchanged from passing R16)
// ---------------------------------------------------------------------------
__global__ void bucket_kernel(const float* __restrict__ rot)
{
    int gid = blockIdx.x * blockDim.x + threadIdx.x;   // < BH*NHASH*T
    int t  = gid & 511;
    int h  = (gid >> 9) & 3;
    int bh = gid >> 11;
    const float* qkb = g_qk + (size_t)(bh >> 3) * T * D + (bh & 7) * DH;

    float s0 = 0.f, s1 = 0.f, s2 = 0.f, s3 = 0.f;
#pragma unroll 8
    for (int d = 0; d < DH; d++) {
        float q = qkb[(size_t)t * D + d];
        const float* rp = rot + d * (NHASH * 4) + h * 4;
        s0 += q * rp[0];
        s1 += q * rp[1];
        s2 += q * rp[2];
        s3 += q * rp[3];
    }
    float cand[8] = {s0, s1, s2, s3, -s0, -s1, -s2, -s3};
    float best = cand[0];
    int bi = 0;
#pragma unroll
    for (int j = 1; j < 8; j++)
        if (cand[j] > best) { best = cand[j]; bi = j; }
    g_bucket[gid] = bi + h * NB;
}

__global__ void place_kernel()
{
    const int bh = blockIdx.x;
    __shared__ int counts[NCHUNK + 1];
    if (threadIdx.x <= NCHUNK) counts[threadIdx.x] = 0;
    __syncthreads();
    for (int i = threadIdx.x; i < NT; i += blockDim.x)
        atomicAdd(&counts[g_bucket[bh * NT + i] + 1], 1);
    __syncthreads();
    if (threadIdx.x == 0)
        for (int i = 1; i <= NCHUNK; i++) counts[i] += counts[i - 1];
    __syncthreads();
    if (threadIdx.x < NCHUNK) {
        int w = threadIdx.x;
        int h = w >> 3;
        int pos = counts[w];
        for (int t = 0; t < T; t++) {
            if (g_bucket[bh * NT + h * T + t] == w) {
                g_st  [bh * NT + pos]       = t;
                g_undo[bh * NT + h * T + t] = pos;
                pos++;
            }
        }
    }
}

__global__ void rnorm_kernel()
{
    int spg = blockIdx.x * blockDim.x + threadIdx.x;   // < BH*NT
    int bh = spg >> 11;
    int t = g_st[spg];
    const float* row = g_qk + (size_t)(bh >> 3) * T * D + (bh & 7) * DH
                       + (size_t)t * D;
    float s = 0.0f;
#pragma unroll 8
    for (int d = 0; d < DH; d++) { float x = row[d]; s += x * x; }
    g_rn[spg] = 1.0f / fmaxf(sqrtf(s), 1e-6f);
}

// ---------------------------------------------------------------------------
// Attention dots, smem-staged: one block per (bh, chunk, q-half).
// smem: Q 8KB + Ks 32.5KB(+pad) + rn/tk ~1KB = ~42.5KB (< 48KB default).
// Writes raw masked scaled dots to g_P (same contract as R16's dots).
// ---------------------------------------------------------------------------
__global__ __launch_bounds__(256)
void dots_kernel()
{
    __shared__ float Q [32 * 64];
    __shared__ float Ks[128 * 65];
    __shared__ float rn[128];
    __shared__ int   tk[128];

    const int qh = blockIdx.x & 1;
    const int c  = (blockIdx.x >> 1) & 31;
    const int bh = blockIdx.x >> 6;
    const int cprev = (c + NCHUNK - 1) & (NCHUNK - 1);
    const float* qkb = g_qk + (size_t)(bh >> 3) * T * D + (bh & 7) * DH;
    const int* stp = g_st + bh * NT;

    for (int i = threadIdx.x; i < 128; i += 256) {
        int kpos = (i < 64) ? (c * 64 + i) : (cprev * 64 + (i - 64));
        tk[i] = stp[kpos];
        rn[i] = g_rn[bh * NT + kpos];
    }
    __syncthreads();

    for (int idx = threadIdx.x; idx < 128 * 64; idx += 256) {
        int r = idx >> 6, d = idx & 63;
        Ks[r * 65 + d] = qkb[(size_t)tk[r] * D + d];
    }
    for (int idx = threadIdx.x; idx < 32 * 64; idx += 256) {
        int qi = idx >> 6, d = idx & 63;
        Q[qi * 64 + d] = qkb[(size_t)tk[qh * 32 + qi] * D + d];
    }
    __syncthreads();

    for (int task = threadIdx.x; task < 32 * 128; task += 256) {
        int qi = task >> 7, kj = task & 127;
        float s = 0.0f;
#pragma unroll 8
        for (int d = 0; d < 64; d++)
            s += Q[qi * 64 + d] * Ks[kj * 65 + d];
        s = s * rn[kj] * 0.125f;
        if (tk[kj] == tk[qh * 32 + qi]) s = MASK_VAL;
        g_P[(size_t)(bh * NT + c * 64 + qh * 32 + qi) * 128 + kj] = s;
    }
}

// ---------------------------------------------------------------------------
// Row softmax + LSE (unchanged)
// ---------------------------------------------------------------------------
__global__ void softmax_kernel()
{
    int gid  = blockIdx.x * blockDim.x + threadIdx.x;
    int row  = gid >> 5;
    int lane = gid & 31;
    float* p = g_P + (size_t)row * 128;
    float v0 = p[lane], v1 = p[lane + 32], v2 = p[lane + 64], v3 = p[lane + 96];
    float m = fmaxf(fmaxf(v0, v1), fmaxf(v2, v3));
#pragma unroll
    for (int o = 16; o > 0; o >>= 1) m = fmaxf(m, __shfl_xor_sync(0xffffffffu, m, o));
    float e0 = expf(v0 - m), e1 = expf(v1 - m), e2 = expf(v2 - m), e3 = expf(v3 - m);
    float ss = e0 + e1 + e2 + e3;
#pragma unroll
    for (int o = 16; o > 0; o >>= 1) ss += __shfl_xor_sync(0xffffffffu, ss, o);
    float inv = 1.0f / ss;
    p[lane]      = e0 * inv;
    p[lane + 32] = e1 * inv;
    p[lane + 64] = e2 * inv;
    p[lane + 96] = e3 * inv;
    if (lane == 0) g_slog[row] = m + logf(ss);
}

// ---------------------------------------------------------------------------
// P @ V, smem-staged V: one block per (bh, chunk). smem ~32.5KB.
// ---------------------------------------------------------------------------
__global__ __launch_bounds__(256)
void pv_kernel()
{
    __shared__ float V[128 * 64];
    __shared__ int   tk[128];

    const int bh = blockIdx.x >> 5;
    const int c  = blockIdx.x & 31;
    const int cprev = (c + NCHUNK - 1) & (NCHUNK - 1);
    const float* vb = g_v + (size_t)(bh >> 3) * T * D + (bh & 7) * DH;
    const int* stp = g_st + bh * NT;

    for (int i = threadIdx.x; i < 128; i += 256)
        tk[i] = (i < 64) ? stp[c * 64 + i] : stp[cprev * 64 + (i - 64)];
    __syncthreads();

    for (int idx = threadIdx.x; idx < 128 * 64; idx += 256) {
        int r = idx >> 6, d = idx & 63;
        V[r * 64 + d] = vb[(size_t)tk[r] * D + d];
    }
    __syncthreads();

    for (int task = threadIdx.x; task < 64 * 64; task += 256) {
        int qi = task >> 6, e = task & 63;
        const float* prow = g_P + (size_t)(bh * NT + c * 64 + qi) * 128;
        float acc = 0.0f;
#pragma unroll 8
        for (int j = 0; j < 128; j++)
            acc += prow[j] * V[j * 64 + e];
        g_so[(size_t)(bh * NT + c * 64 + qi) * DH + e] = acc;
    }
}

__global__ void merge_kernel()
{
    int gid = blockIdx.x * blockDim.x + threadIdx.x;
    int gwarp = gid >> 5, lane = gid & 31;
    int bh = gwarp >> 9;
    int t  = gwarp & (T - 1);
    int base = bh * NT;

    float lg[4]; int jj[4];
#pragma unroll
    for (int h = 0; h < 4; h++) {
        jj[h] = g_undo[base + h * T + t];
        lg[h] = g_slog[base + jj[h]];
    }
    float m = fmaxf(fmaxf(lg[0], lg[1]), fmaxf(lg[2], lg[3]));
    float e0 = expf(lg[0] - m), e1 = expf(lg[1] - m), e2 = expf(lg[2] - m), e3 = expf(lg[3] - m);
    float inv = 1.0f / (e0 + e1 + e2 + e3);
    float w0 = e0 * inv, w1 = e1 * inv, w2 = e2 * inv, w3 = e3 * inv;

    const float* s0 = g_so + (size_t)(base + jj[0]) * DH;
    const float* s1 = g_so + (size_t)(base + jj[1]) * DH;
    const float* s2 = g_so + (size_t)(base + jj[2]) * DH;
    const float* s3 = g_so + (size_t)(base + jj[3]) * DH;

    int b = bh >> 3, h8 = bh & 7;
    float* dst = g_ctx + (size_t)(b * T + t) * D + h8 * DH;
#pragma unroll
    for (int e = lane; e < DH; e += 32)
        dst[e] = w0 * s0[e] + w1 * s1[e] + w2 * s2[e] + w3 * s3[e];
}

__global__ void cls_kernel(const float* __restrict__ cw,
                           const float* __restrict__ cb,
                           float* __restrict__ out)
{
    int warp = threadIdx.x >> 5, lane = threadIdx.x & 31;
    int b = warp >> 1, n = warp & 1;
    const float* p1 = g_x1 + (size_t)b * T * D;
    const float* p2 = g_x2 + (size_t)b * T * D;
    float s = 0.0f;
    for (int d = lane; d < D; d += 32)
        s += (p1[d] + p2[d]) * cw[d * NLABELS + n];
#pragma unroll
    for (int o = 16; o > 0; o >>= 1) s += __shfl_xor_sync(0xffffffffu, s, o);
    if (lane == 0) out[b * NLABELS + n] = s + cb[n];
}

// ---------------------------------------------------------------------------
// Launch sequence — identical skeleton to the passing R16, with tiled sgemm
// replacing nmm and smem-staged dots/pv.
// ---------------------------------------------------------------------------
extern "C" void kernel_launch(void* const* d_in, const int* in_sizes, int n_in,
                              void* d_out, int out_size)
{
    const int*   ids   = (const int*)  d_in[0];
    const float* tok   = (const float*)d_in[1];
    const float* pos   = (const float*)d_in[2];
    const float* rot   = (const float*)d_in[3];
    const float* Wqk   = (const float*)d_in[4];
    const float* Wv    = (const float*)d_in[5];
    const float* Wout  = (const float*)d_in[6];
    const float* bout  = (const float*)d_in[7];
    const float* lnf_s = (const float*)d_in[8];
    const float* lnf_b = (const float*)d_in[9];
    const float* lng_s = (const float*)d_in[10];
    const float* lng_b = (const float*)d_in[11];
    const float* fw1   = (const float*)d_in[12];
    const float* fb1   = (const float*)d_in[13];
    const float* fw2   = (const float*)d_in[14];
    const float* fb2   = (const float*)d_in[15];
    const float* cw    = (const float*)d_in[16];
    const float* cb    = (const float*)d_in[17];
    float* out = (float*)d_out;

    void *vp;
    float *p_x1, *p_x2, *p_xn, *p_qk, *p_v, *p_ctx, *p_ff;
    cudaGetSymbolAddress(&vp, g_x1);  p_x1  = (float*)vp;
    cudaGetSymbolAddress(&vp, g_x2);  p_x2  = (float*)vp;
    cudaGetSymbolAddress(&vp, g_xn);  p_xn  = (float*)vp;
    cudaGetSymbolAddress(&vp, g_qk);  p_qk  = (float*)vp;
    cudaGetSymbolAddress(&vp, g_v);   p_v   = (float*)vp;
    cudaGetSymbolAddress(&vp, g_ctx); p_ctx = (float*)vp;
    cudaGetSymbolAddress(&vp, g_ff);  p_ff  = (float*)vp;

    embed_kernel<<<(ROWS * D) / 256, 256>>>(ids, tok, pos);

    dim3 gD (D  / 128, ROWS / 128);   // (4, 64)
    dim3 gF1(FF / 128, ROWS / 128);   // (16, 64)
    dim3 gF2(D  / 128, ROWS / 128);   // (4, 64)

    for (int l = 0; l < DEPTH; l++) {
        const float* wqk = Wqk + (size_t)l * D * D;
        const float* wv  = Wv  + (size_t)l * D * D;
        const float* wo  = Wout + (size_t)l * D * D;
        const float* w1  = fw1 + (size_t)l * D * FF;
        const float* w2  = fw2 + (size_t)l * FF * D;

        ln_kernel<<<ROWS, 256>>>(p_x2, lnf_s + l * D, lnf_b + l * D, p_xn);
        sgemm_kernel<0><<<gD, 256>>>(p_xn, wqk, p_qk, nullptr, nullptr, D, D);
        sgemm_kernel<0><<<gD, 256>>>(p_xn, wv,  p_v,  nullptr, nullptr, D, D);
        bucket_kernel<<<(BH * NHASH * T) / 256, 256>>>(rot + (size_t)l * DH * NHASH * 4);
        place_kernel<<<BH, 256>>>();
        rnorm_kernel<<<(BH * NT) / 256, 256>>>();
        dots_kernel<<<BH * NCHUNK * 2, 256>>>();
        softmax_kernel<<<(BH * NT * 32) / 256, 256>>>();
        pv_kernel<<<BH * NCHUNK, 256>>>();
        merge_kernel<<<(BH * T) / 8, 256>>>();
        sgemm_kernel<3><<<gD, 256>>>(p_ctx, wo, p_x1, bout + l * D, p_x1, D, D);
        ln_kernel<<<ROWS, 256>>>(p_x1, lng_s + l * D, lng_b + l * D, p_xn);
        sgemm_kernel<2><<<gF1, 256>>>(p_xn, w1, p_ff, fb1 + l * FF, nullptr, FF, D);
        sgemm_kernel<3><<<gF2, 256>>>(p_ff, w2, p_x2, fb2 + l * D, p_x2, D, FF);
    }

    cls_kernel<<<1, 1024>>>(cw, cb, out);
}